// round 12
// baseline (speedup 1.0000x reference)
#include <cuda_runtime.h>
#include <cuda_fp16.h>
#include <cstdint>

// ---------------------------------------------------------------------------
// Problem constants
// ---------------------------------------------------------------------------
#define OC      8192
#define IC      8192
#define BATCH   64
#define PROWS   4096      // packed rows (OC/2)
#define NSLOT   5         // max k-splits per tile (balanced 296-CTA grid)

// ---- GEMM config (mma.sync m16n8k16 fp16, plain sm_103) ----
#define TILE_P     64                 // packed rows per CTA -> 128 oc
#define KC         128                // k per chunk
#define SB_STRIDE  136                // fp16 per B row (128 + 8 pad)
#define STAGE_B_BYTES (BATCH * SB_STRIDE * 2)           // 17408 per stage (B only)
#define SMEM_TOTAL    (2 * STAGE_B_BYTES)               // 34816 (epilogue needs 33792)

// ---------------------------------------------------------------------------
// Scratch (device globals; allocation-free contract)
// g_partial slot 4 is only written by 5-split tiles (0..39); for tiles 40..63
// it keeps its zero initialization -> deterministic, and reduce adds 0.
// ---------------------------------------------------------------------------
__device__ __half g_xh[BATCH * IC];                    // fp16 activations [64][8192]
__device__ float  g_Spart[512];                        // row-sum partials [64 b][8 chunks]
__device__ float  g_partial[NSLOT * BATCH * OC];       // [5][64][8192]

// ---------------------------------------------------------------------------
// Helpers
// ---------------------------------------------------------------------------
__device__ __forceinline__ uint32_t smem_u32(const void* p) {
    uint32_t a;
    asm("{ .reg .u64 t; cvta.to.shared.u64 t, %1; cvt.u32.u64 %0, t; }" : "=r"(a) : "l"(p));
    return a;
}

__device__ __forceinline__ void cp16(uint32_t dst, const void* src) {
    asm volatile("cp.async.cg.shared.global [%0], [%1], 16;" :: "r"(dst), "l"(src));
}
#define CP_COMMIT() asm volatile("cp.async.commit_group;" ::: "memory")
#define CP_WAIT1()  asm volatile("cp.async.wait_group 1;" ::: "memory")

__device__ __forceinline__ void mma16816(float* c, const uint32_t* a, const uint32_t* b) {
    asm volatile("mma.sync.aligned.m16n8k16.row.col.f32.f16.f16.f32 "
                 "{%0,%1,%2,%3}, {%4,%5,%6,%7}, {%8,%9}, {%0,%1,%2,%3};"
                 : "+f"(c[0]), "+f"(c[1]), "+f"(c[2]), "+f"(c[3])
                 : "r"(a[0]), "r"(a[1]), "r"(a[2]), "r"(a[3]), "r"(b[0]), "r"(b[1]));
}

// ---------------------------------------------------------------------------
// Kernel 1: x -> fp16 (vectorized), partial row sums OF THE ROUNDED VALUES
// (so the +64 dequant offset cancels exactly in the reduce). 512 CTAs.
// ---------------------------------------------------------------------------
__global__ void prep_kernel(const float* __restrict__ x) {
    __shared__ float red[8];
    const int b  = blockIdx.x >> 3;
    const int c0 = (blockIdx.x & 7) * 1024 + threadIdx.x * 4;
    const float4 v = *(const float4*)(x + b * IC + c0);
    const __half h0 = __float2half(v.x), h1 = __float2half(v.y);
    const __half h2 = __float2half(v.z), h3 = __float2half(v.w);
    __half2 p0 = __halves2half2(h0, h1), p1 = __halves2half2(h2, h3);
    uint2 st;
    st.x = *(uint32_t*)&p0; st.y = *(uint32_t*)&p1;
    *(uint2*)(g_xh + b * IC + c0) = st;
    float s = (__half2float(h0) + __half2float(h1))
            + (__half2float(h2) + __half2float(h3));
    #pragma unroll
    for (int o = 16; o > 0; o >>= 1)
        s += __shfl_xor_sync(0xFFFFFFFFu, s, o);
    if ((threadIdx.x & 31) == 0) red[threadIdx.x >> 5] = s;
    __syncthreads();
    if (threadIdx.x == 0) {
        float t = 0.f;
        #pragma unroll
        for (int j = 0; j < 8; ++j) t += red[j];
        g_Spart[blockIdx.x] = t;
    }
}

// ---------------------------------------------------------------------------
// Kernel 2: fused int4-dequant + fp16 mma.sync GEMM.
//   Balanced 296-CTA grid (R11). B (activations) via 2-stage cp.async smem
//   pipeline (R7-proven). A (packed weights) loaded DIRECTLY from global via
//   per-warp LDG.64 with a one-kk-ahead register prefetch — removes A from
//   smem entirely (smem traffic per chunk drops ~2.2x; was the binder).
//   The wc-duplicate A read hits L1/L2; DRAM still streams A exactly once.
//   Dequant: fp16 bits 0x5400|(q<<4) == 64+q exactly; offset cancels via S.
// ---------------------------------------------------------------------------
__global__ void __launch_bounds__(256, 2)
gemm_kernel(const int* __restrict__ packed) {
    extern __shared__ char smem[];
    const uint32_t smem_b32 = smem_u32(smem);
    const int tid  = threadIdx.x;
    const int wid  = tid >> 5, lane = tid & 31;
    const int g    = lane >> 2, t = lane & 3;
    const int wr   = wid & 3,  wc = wid >> 2;

    // ---- balanced work decode (R11) ----
    const int bid = blockIdx.x;
    int tile, slot, chunk0, nch;
    if (bid < 200) {
        tile   = bid / 5;
        slot   = bid - tile * 5;
        nch    = (slot < 4) ? 13 : 12;
        chunk0 = slot * 13;
    } else {
        const int b2 = bid - 200;
        tile   = 40 + (b2 >> 2);
        slot   = b2 & 3;
        nch    = 16;
        chunk0 = slot << 4;
    }
    const int p0 = tile * TILE_P;
    const int k0 = chunk0 * KC;

    // per-lane A base: row (p0 + wr*16 + g), col (k0 + 2t)
    const int* aptr = packed + (long)(p0 + wr * 16 + g) * IC + k0 + 2 * t;

    // load the 4 A int2s for global k-step kg (16 k per step)
    auto ldA = [&](int kg, int2* dst) {
        #pragma unroll
        for (int kh = 0; kh < 2; ++kh)
            #pragma unroll
            for (int hr = 0; hr < 2; ++hr)
                dst[hr + 2 * kh] = *(const int2*)(aptr + hr * 8 * IC + kg * 16 + kh * 8);
    };

    float accL[4][4], accH[4][4];
    #pragma unroll
    for (int j = 0; j < 4; ++j)
        #pragma unroll
        for (int q = 0; q < 4; ++q) { accL[j][q] = 0.f; accH[j][q] = 0.f; }

    auto issueB = [&](int c) {
        const int s = c & 1;
        const int kc = k0 + c * KC;
        const uint32_t sb = smem_b32 + s * STAGE_B_BYTES;
        #pragma unroll
        for (int j = 0; j < 4; ++j) {               // B: 64 rows x 256B = 1024 cp16
            const int i = tid + j * 256;
            const int r = i >> 4, si = i & 15;
            cp16(sb + (uint32_t)(r * SB_STRIDE + si * 8) * 2,
                 g_xh + (long)r * IC + kc + si * 8);
        }
        CP_COMMIT();
    };

    const int totkk = nch * 8;
    int2 apre[4];
    ldA(0, apre);
    issueB(0);

    for (int c = 0; c < nch; ++c) {
        if (c + 1 < nch) issueB(c + 1);
        else CP_COMMIT();                 // keep group count uniform
        CP_WAIT1();                       // B chunk c resident
        __syncthreads();

        const char* B = smem + (c & 1) * STAGE_B_BYTES;

        #pragma unroll
        for (int kk = 0; kk < 8; ++kk) {
            // consume prefetched A, kick off next prefetch
            int2 acur[4];
            #pragma unroll
            for (int i = 0; i < 4; ++i) acur[i] = apre[i];
            const int kg = c * 8 + kk + 1;
            if (kg < totkk) ldA(kg, apre);

            uint32_t afl[4], afh[4];
            #pragma unroll
            for (int i = 0; i < 4; ++i) {
                afl[i] = (((uint32_t)acur[i].x << 4) & 0xF0u)
                       | (((uint32_t)acur[i].y << 20) & 0xF00000u) | 0x54005400u;
                afh[i] = ((uint32_t)acur[i].x & 0xF0u)
                       | (((uint32_t)acur[i].y << 16) & 0xF00000u) | 0x54005400u;
            }
            #pragma unroll
            for (int nf = 0; nf < 4; ++nf) {
                const int n = wc * 32 + nf * 8 + g;
                uint32_t bf[2];
                bf[0] = *(const uint32_t*)(B + (n * SB_STRIDE + kk * 16 + 2 * t) * 2);
                bf[1] = *(const uint32_t*)(B + (n * SB_STRIDE + kk * 16 + 2 * t + 8) * 2);
                mma16816(accL[nf], afl, bf);
                mma16816(accH[nf], afh, bf);
            }
        }
        __syncthreads();
    }

    // ---- epilogue: transpose through smem, then coalesced float4 stores ----
    float* sm = (float*)smem;                  // [64 b][132] (pad 4) = 33792B <= 34816
    #pragma unroll
    for (int nf = 0; nf < 4; ++nf)
        #pragma unroll
        for (int q = 0; q < 4; ++q) {
            const int mrow = wr * 16 + g + (q >> 1) * 8;              // 0..63
            const int b    = wc * 32 + nf * 8 + 2 * t + (q & 1);      // 0..63
            sm[b * 132 + mrow]      = accL[nf][q];                    // low nibble
            sm[b * 132 + 64 + mrow] = accH[nf][q];                    // high nibble
        }
    __syncthreads();
    #pragma unroll
    for (int j = 0; j < 8; ++j) {
        const int i = tid + j * 256;           // 2048 float4
        const int b  = i >> 5;
        const int mv = (i & 31) * 4;
        const float4 v = *(const float4*)(sm + b * 132 + mv);
        const long oc = (mv < 64) ? (long)(p0 + mv) : (long)(PROWS + p0 + mv - 64);
        *(float4*)(g_partial + (((long)(slot * BATCH + b)) << 13) + oc) = v;
    }
}

// ---------------------------------------------------------------------------
// Kernel 3: sum the 5 k-slots + affine epilogue (vectorized float4 over oc)
//   out[b,oc] = delta[oc] * (dot' - (zp[oc]+64)*S_h[b]) + bias[oc]
// ---------------------------------------------------------------------------
__global__ void reduce_kernel(const float* __restrict__ delta,
                              const float* __restrict__ zp,
                              const float* __restrict__ bias,
                              float* __restrict__ out) {
    const int idx4 = (blockIdx.x * 256 + threadIdx.x) * 4;  // b*8192 + oc
    const int b  = idx4 >> 13;
    const int oc = idx4 & (OC - 1);
    float4 dot = make_float4(0.f, 0.f, 0.f, 0.f);
    #pragma unroll
    for (int s = 0; s < NSLOT; ++s) {
        const float4 p = *(const float4*)(g_partial + (long)(s * BATCH + b) * OC + oc);
        dot.x += p.x; dot.y += p.y; dot.z += p.z; dot.w += p.w;
    }
    float S = 0.f;
    #pragma unroll
    for (int j = 0; j < 8; ++j) S += g_Spart[b * 8 + j];
    const float4 d  = *(const float4*)(delta + oc);
    const float4 z  = *(const float4*)(zp + oc);
    const float4 bi = *(const float4*)(bias + oc);
    float4 o;
    o.x = d.x * (dot.x - (z.x + 64.f) * S) + bi.x;
    o.y = d.y * (dot.y - (z.y + 64.f) * S) + bi.y;
    o.z = d.z * (dot.z - (z.z + 64.f) * S) + bi.z;
    o.w = d.w * (dot.w - (z.w + 64.f) * S) + bi.w;
    *(float4*)(out + idx4) = o;
}

// ---------------------------------------------------------------------------
// Launch
// ---------------------------------------------------------------------------
extern "C" void kernel_launch(void* const* d_in, const int* in_sizes, int n_in,
                              void* d_out, int out_size) {
    const float* x      = (const float*)d_in[0];
    const int*   packed = (const int*)d_in[1];
    const float* delta  = (const float*)d_in[2];
    const float* zp     = (const float*)d_in[3];
    const float* bias   = (const float*)d_in[4];
    float* out = (float*)d_out;

    cudaFuncSetAttribute(gemm_kernel, cudaFuncAttributeMaxDynamicSharedMemorySize, SMEM_TOTAL);

    prep_kernel<<<512, 256>>>(x);
    gemm_kernel<<<296, 256, SMEM_TOTAL>>>(packed);
    reduce_kernel<<<(BATCH * OC) / 1024, 256>>>(delta, zp, bias, out);
}

// round 13
// speedup vs baseline: 1.7512x; 1.7512x over previous
#include <cuda_runtime.h>
#include <cuda_fp16.h>
#include <cstdint>

// ---------------------------------------------------------------------------
// Problem constants
// ---------------------------------------------------------------------------
#define OC      8192
#define IC      8192
#define BATCH   64
#define PROWS   4096      // packed rows (OC/2)
#define NSLOT   5         // max k-splits per tile (balanced 296-CTA grid)

// ---- GEMM config (mma.sync m16n8k16 fp16, plain sm_103) ----
#define TILE_P     64                 // packed rows per CTA -> 128 oc
#define KC         128                // k per chunk
#define SA_STRIDE  136                // ints per A row (128 + 8 pad; %32=8 -> conflict-free)
#define SB_STRIDE  136                // fp16 per B row (128 + 8 pad)
#define STAGE_A_BYTES (TILE_P * SA_STRIDE * 4)          // 34816
#define STAGE_B_BYTES (BATCH * SB_STRIDE * 2)           // 17408
#define STAGE_BYTES   (STAGE_A_BYTES + STAGE_B_BYTES)   // 52224
#define SMEM_TOTAL    (2 * STAGE_BYTES)                 // 104448 -> occ 2 = 209KB/SM

// ---------------------------------------------------------------------------
// Scratch (device globals; allocation-free contract)
// g_partial slot 4 is only written by 5-split tiles (0..39); for tiles 40..63
// it keeps its zero initialization -> deterministic, and reduce adds 0.
// ---------------------------------------------------------------------------
__device__ __half g_xh[BATCH * IC];                    // fp16 activations [64][8192]
__device__ float  g_Spart[512];                        // row-sum partials [64 b][8 chunks]
__device__ float  g_partial[NSLOT * BATCH * OC];       // [5][64][8192]

// ---------------------------------------------------------------------------
// Helpers
// ---------------------------------------------------------------------------
__device__ __forceinline__ uint32_t smem_u32(const void* p) {
    uint32_t a;
    asm("{ .reg .u64 t; cvta.to.shared.u64 t, %1; cvt.u32.u64 %0, t; }" : "=r"(a) : "l"(p));
    return a;
}

__device__ __forceinline__ void cp16(uint32_t dst, const void* src) {
    asm volatile("cp.async.cg.shared.global [%0], [%1], 16;" :: "r"(dst), "l"(src));
}
#define CP_COMMIT() asm volatile("cp.async.commit_group;" ::: "memory")
#define CP_WAIT1()  asm volatile("cp.async.wait_group 1;" ::: "memory")

__device__ __forceinline__ void mma16816(float* c, const uint32_t* a, const uint32_t* b) {
    asm volatile("mma.sync.aligned.m16n8k16.row.col.f32.f16.f16.f32 "
                 "{%0,%1,%2,%3}, {%4,%5,%6,%7}, {%8,%9}, {%0,%1,%2,%3};"
                 : "+f"(c[0]), "+f"(c[1]), "+f"(c[2]), "+f"(c[3])
                 : "r"(a[0]), "r"(a[1]), "r"(a[2]), "r"(a[3]), "r"(b[0]), "r"(b[1]));
}

// ---------------------------------------------------------------------------
// Kernel 1: x -> fp16 (vectorized), partial row sums OF THE ROUNDED VALUES
// (so the +64 dequant offset cancels exactly in the reduce). 512 CTAs.
// ---------------------------------------------------------------------------
__global__ void prep_kernel(const float* __restrict__ x) {
    __shared__ float red[8];
    const int b  = blockIdx.x >> 3;
    const int c0 = (blockIdx.x & 7) * 1024 + threadIdx.x * 4;
    const float4 v = *(const float4*)(x + b * IC + c0);
    const __half h0 = __float2half(v.x), h1 = __float2half(v.y);
    const __half h2 = __float2half(v.z), h3 = __float2half(v.w);
    __half2 p0 = __halves2half2(h0, h1), p1 = __halves2half2(h2, h3);
    uint2 st;
    st.x = *(uint32_t*)&p0; st.y = *(uint32_t*)&p1;
    *(uint2*)(g_xh + b * IC + c0) = st;
    float s = (__half2float(h0) + __half2float(h1))
            + (__half2float(h2) + __half2float(h3));
    #pragma unroll
    for (int o = 16; o > 0; o >>= 1)
        s += __shfl_xor_sync(0xFFFFFFFFu, s, o);
    if ((threadIdx.x & 31) == 0) red[threadIdx.x >> 5] = s;
    __syncthreads();
    if (threadIdx.x == 0) {
        float t = 0.f;
        #pragma unroll
        for (int j = 0; j < 8; ++j) t += red[j];
        g_Spart[blockIdx.x] = t;
    }
}

// ---------------------------------------------------------------------------
// Kernel 2: fused int4-dequant + fp16 mma.sync GEMM (R11-proven).
//   Balanced 296-CTA grid = exactly 2 CTAs per SM via LUT[bid%148].
//   Work decode: bids 0..199   -> tiles 0..39,  5 splits {13,13,13,13,12}
//                bids 200..295 -> tiles 40..63, 4 splits {16,16,16,16}
//   Warp (wr 0..3, wc 0..1): wr owns 16 packed rows, extracts BOTH nibbles
//   from one int2 LDS; wc owns 32 batch. Conflict-free strides, KC=128,
//   2-stage cp.async, two syncs per chunk.
//   Dequant: fp16 bits 0x5400|(q<<4) == 64+q exactly; offset cancels via S.
// ---------------------------------------------------------------------------
__global__ void __launch_bounds__(256, 2)
gemm_kernel(const int* __restrict__ packed) {
    extern __shared__ char smem[];
    const uint32_t smem_b32 = smem_u32(smem);
    const int tid  = threadIdx.x;
    const int wid  = tid >> 5, lane = tid & 31;
    const int g    = lane >> 2, t = lane & 3;
    const int wr   = wid & 3,  wc = wid >> 2;

    // ---- balanced work decode ----
    const int bid = blockIdx.x;
    int tile, slot, chunk0, nch;
    if (bid < 200) {
        tile   = bid / 5;
        slot   = bid - tile * 5;
        nch    = (slot < 4) ? 13 : 12;
        chunk0 = slot * 13;
    } else {
        const int b2 = bid - 200;
        tile   = 40 + (b2 >> 2);
        slot   = b2 & 3;
        nch    = 16;
        chunk0 = slot << 4;
    }
    const int p0 = tile * TILE_P;
    const int k0 = chunk0 * KC;

    float accL[4][4], accH[4][4];
    #pragma unroll
    for (int j = 0; j < 4; ++j)
        #pragma unroll
        for (int q = 0; q < 4; ++q) { accL[j][q] = 0.f; accH[j][q] = 0.f; }

    auto issue = [&](int c) {
        const int s = c & 1;
        const int kc = k0 + c * KC;
        const uint32_t sa = smem_b32 + s * STAGE_BYTES;
        const uint32_t sb = sa + STAGE_A_BYTES;
        #pragma unroll
        for (int j = 0; j < 8; ++j) {               // A: 64 rows x 512B
            const int i = tid + j * 256;
            const int r = i >> 5, si = i & 31;
            cp16(sa + (uint32_t)(r * SA_STRIDE + si * 4) * 4,
                 packed + (long)(p0 + r) * IC + kc + si * 4);
        }
        #pragma unroll
        for (int j = 0; j < 4; ++j) {               // B: 64 rows x 256B
            const int i = tid + j * 256;
            const int r = i >> 4, si = i & 15;
            cp16(sb + (uint32_t)(r * SB_STRIDE + si * 8) * 2,
                 g_xh + (long)r * IC + kc + si * 8);
        }
        CP_COMMIT();
    };

    issue(0);
    for (int c = 0; c < nch; ++c) {
        if (c + 1 < nch) issue(c + 1);
        else CP_COMMIT();                 // keep group count uniform
        CP_WAIT1();                       // chunk c resident
        __syncthreads();

        const char* A = smem + (c & 1) * STAGE_BYTES;
        const char* B = A + STAGE_A_BYTES;

        #pragma unroll
        for (int kk = 0; kk < 8; ++kk) {
            uint32_t afl[4], afh[4];
            #pragma unroll
            for (int kh = 0; kh < 2; ++kh) {
                #pragma unroll
                for (int hr = 0; hr < 2; ++hr) {
                    const int2 v = *(const int2*)(A + ((wr * 16 + g + hr * 8) * SA_STRIDE
                                                      + kk * 16 + 2 * t + kh * 8) * 4);
                    const int idx = hr + 2 * kh;
                    afl[idx] = (((uint32_t)v.x << 4) & 0xF0u)
                             | (((uint32_t)v.y << 20) & 0xF00000u) | 0x54005400u;
                    afh[idx] = ((uint32_t)v.x & 0xF0u)
                             | (((uint32_t)v.y << 16) & 0xF00000u) | 0x54005400u;
                }
            }
            #pragma unroll
            for (int nf = 0; nf < 4; ++nf) {
                const int n = wc * 32 + nf * 8 + g;
                uint32_t bf[2];
                bf[0] = *(const uint32_t*)(B + (n * SB_STRIDE + kk * 16 + 2 * t) * 2);
                bf[1] = *(const uint32_t*)(B + (n * SB_STRIDE + kk * 16 + 2 * t + 8) * 2);
                mma16816(accL[nf], afl, bf);
                mma16816(accH[nf], afh, bf);
            }
        }
        __syncthreads();
    }

    // ---- epilogue: transpose through smem, then coalesced float4 stores ----
    float* sm = (float*)smem;                  // [64 b][132] (pad 4) = 33792B
    #pragma unroll
    for (int nf = 0; nf < 4; ++nf)
        #pragma unroll
        for (int q = 0; q < 4; ++q) {
            const int mrow = wr * 16 + g + (q >> 1) * 8;              // 0..63
            const int b    = wc * 32 + nf * 8 + 2 * t + (q & 1);      // 0..63
            sm[b * 132 + mrow]      = accL[nf][q];                    // low nibble
            sm[b * 132 + 64 + mrow] = accH[nf][q];                    // high nibble
        }
    __syncthreads();
    #pragma unroll
    for (int j = 0; j < 8; ++j) {
        const int i = tid + j * 256;           // 2048 float4
        const int b  = i >> 5;
        const int mv = (i & 31) * 4;
        const float4 v = *(const float4*)(sm + b * 132 + mv);
        const long oc = (mv < 64) ? (long)(p0 + mv) : (long)(PROWS + p0 + mv - 64);
        *(float4*)(g_partial + (((long)(slot * BATCH + b)) << 13) + oc) = v;
    }
}

// ---------------------------------------------------------------------------
// Kernel 3: sum the 5 k-slots + affine epilogue (vectorized float4 over oc)
//   out[b,oc] = delta[oc] * (dot' - (zp[oc]+64)*S_h[b]) + bias[oc]
// ---------------------------------------------------------------------------
__global__ void reduce_kernel(const float* __restrict__ delta,
                              const float* __restrict__ zp,
                              const float* __restrict__ bias,
                              float* __restrict__ out) {
    const int idx4 = (blockIdx.x * 256 + threadIdx.x) * 4;  // b*8192 + oc
    const int b  = idx4 >> 13;
    const int oc = idx4 & (OC - 1);
    float4 dot = make_float4(0.f, 0.f, 0.f, 0.f);
    #pragma unroll
    for (int s = 0; s < NSLOT; ++s) {
        const float4 p = *(const float4*)(g_partial + (long)(s * BATCH + b) * OC + oc);
        dot.x += p.x; dot.y += p.y; dot.z += p.z; dot.w += p.w;
    }
    float S = 0.f;
    #pragma unroll
    for (int j = 0; j < 8; ++j) S += g_Spart[b * 8 + j];
    const float4 d  = *(const float4*)(delta + oc);
    const float4 z  = *(const float4*)(zp + oc);
    const float4 bi = *(const float4*)(bias + oc);
    float4 o;
    o.x = d.x * (dot.x - (z.x + 64.f) * S) + bi.x;
    o.y = d.y * (dot.y - (z.y + 64.f) * S) + bi.y;
    o.z = d.z * (dot.z - (z.z + 64.f) * S) + bi.z;
    o.w = d.w * (dot.w - (z.w + 64.f) * S) + bi.w;
    *(float4*)(out + idx4) = o;
}

// ---------------------------------------------------------------------------
// Launch
// ---------------------------------------------------------------------------
extern "C" void kernel_launch(void* const* d_in, const int* in_sizes, int n_in,
                              void* d_out, int out_size) {
    const float* x      = (const float*)d_in[0];
    const int*   packed = (const int*)d_in[1];
    const float* delta  = (const float*)d_in[2];
    const float* zp     = (const float*)d_in[3];
    const float* bias   = (const float*)d_in[4];
    float* out = (float*)d_out;

    cudaFuncSetAttribute(gemm_kernel, cudaFuncAttributeMaxDynamicSharedMemorySize, SMEM_TOTAL);

    prep_kernel<<<512, 256>>>(x);
    gemm_kernel<<<296, 256, SMEM_TOTAL>>>(packed);
    reduce_kernel<<<(BATCH * OC) / 1024, 256>>>(delta, zp, bias, out);
}

// round 15
// speedup vs baseline: 1.8620x; 1.0633x over previous
#include <cuda_runtime.h>
#include <cuda_fp16.h>
#include <cstdint>

// ---------------------------------------------------------------------------
// Problem constants
// ---------------------------------------------------------------------------
#define OC      8192
#define IC      8192
#define BATCH   64
#define PROWS   4096      // packed rows (OC/2)
#define NSLOT   5         // max k-splits per tile (balanced 296-CTA grid)

// ---- GEMM config (mma.sync m16n8k16 fp16, plain sm_103) ----
#define TILE_P     64                 // packed rows per CTA -> 128 oc
#define KC         128                // k per chunk
#define PA_STRIDE  136                // bytes per packed-A row (128 + 8 pad)
#define PA_STAGE   (TILE_P * PA_STRIDE)                 // 8704
#define SB_STRIDE  136                // fp16 per B row (128 + 8 pad)
#define STAGE_B_BYTES (BATCH * SB_STRIDE * 2)           // 17408
#define SMEM_B_OFF    (2 * PA_STAGE)                    // 17408
#define SMEM_TOTAL    (2 * PA_STAGE + 2 * STAGE_B_BYTES) // 52224 (epilogue needs 33792)

// ---------------------------------------------------------------------------
// Scratch (device globals; allocation-free contract)
// g_partial slot 4 is only written by 5-split tiles (0..39); for tiles 40..63
// it keeps its zero initialization -> deterministic, and reduce adds 0.
// ---------------------------------------------------------------------------
__device__ __half g_xh[BATCH * IC];                    // fp16 activations [64][8192]
__device__ float  g_Spart[512];                        // row-sum partials [64 b][8 chunks]
__device__ float  g_partial[NSLOT * BATCH * OC];       // [5][64][8192]

// ---------------------------------------------------------------------------
// Helpers
// ---------------------------------------------------------------------------
__device__ __forceinline__ uint32_t smem_u32(const void* p) {
    uint32_t a;
    asm("{ .reg .u64 t; cvta.to.shared.u64 t, %1; cvt.u32.u64 %0, t; }" : "=r"(a) : "l"(p));
    return a;
}

__device__ __forceinline__ void cp16(uint32_t dst, const void* src) {
    asm volatile("cp.async.cg.shared.global [%0], [%1], 16;" :: "r"(dst), "l"(src));
}
#define CP_COMMIT() asm volatile("cp.async.commit_group;" ::: "memory")
#define CP_WAIT1()  asm volatile("cp.async.wait_group 1;" ::: "memory")

__device__ __forceinline__ void mma16816(float* c, const uint32_t* a, const uint32_t* b) {
    asm volatile("mma.sync.aligned.m16n8k16.row.col.f32.f16.f16.f32 "
                 "{%0,%1,%2,%3}, {%4,%5,%6,%7}, {%8,%9}, {%0,%1,%2,%3};"
                 : "+f"(c[0]), "+f"(c[1]), "+f"(c[2]), "+f"(c[3])
                 : "r"(a[0]), "r"(a[1]), "r"(a[2]), "r"(a[3]), "r"(b[0]), "r"(b[1]));
}

// ---------------------------------------------------------------------------
// Kernel 1: x -> fp16 (vectorized), partial row sums OF THE ROUNDED VALUES
// (so the +64 dequant offset cancels exactly in the reduce). 512 CTAs.
// ---------------------------------------------------------------------------
__global__ void prep_kernel(const float* __restrict__ x) {
    __shared__ float red[8];
    const int b  = blockIdx.x >> 3;
    const int c0 = (blockIdx.x & 7) * 1024 + threadIdx.x * 4;
    const float4 v = *(const float4*)(x + b * IC + c0);
    const __half h0 = __float2half(v.x), h1 = __float2half(v.y);
    const __half h2 = __float2half(v.z), h3 = __float2half(v.w);
    __half2 p0 = __halves2half2(h0, h1), p1 = __halves2half2(h2, h3);
    uint2 st;
    st.x = *(uint32_t*)&p0; st.y = *(uint32_t*)&p1;
    *(uint2*)(g_xh + b * IC + c0) = st;
    float s = (__half2float(h0) + __half2float(h1))
            + (__half2float(h2) + __half2float(h3));
    #pragma unroll
    for (int o = 16; o > 0; o >>= 1)
        s += __shfl_xor_sync(0xFFFFFFFFu, s, o);
    if ((threadIdx.x & 31) == 0) red[threadIdx.x >> 5] = s;
    __syncthreads();
    if (threadIdx.x == 0) {
        float t = 0.f;
        #pragma unroll
        for (int j = 0; j < 8; ++j) t += red[j];
        g_Spart[blockIdx.x] = t;
    }
}

// ---------------------------------------------------------------------------
// Kernel 2: fused int4-dequant + fp16 mma.sync GEMM.
//   Balanced 296-CTA grid (R11). B via 2-stage cp.async (R7-proven).
//   A: each int32 of weight_packed holds ONE useful byte -> LDG int4 into a
//   per-chunk REGISTER buffer, PRMT-pack 4 bytes/word, STS.32 into a byte-
//   packed smem tile [64][136B]. A smem traffic drops 4x (per-chunk smem
//   112KB -> 24KB; total 176 -> 104KB), removing the smem-port bottleneck.
//   LDG(c+1) is issued after the mid-sync and consumed at the TOP of the next
//   iteration -> a full chunk (~800cyc) of latency cover (fixes R12 mistake).
//   Dequant: fp16 bits 0x5400|(q<<4) == 64+q exactly; offset cancels via S.
// ---------------------------------------------------------------------------
__global__ void __launch_bounds__(256, 2)
gemm_kernel(const int* __restrict__ packed) {
    extern __shared__ char smem[];
    const uint32_t smem_b32 = smem_u32(smem);
    const int tid  = threadIdx.x;
    const int wid  = tid >> 5, lane = tid & 31;
    const int g    = lane >> 2, t = lane & 3;
    const int wr   = wid & 3,  wc = wid >> 2;

    // ---- balanced work decode (R11) ----
    const int bid = blockIdx.x;
    int tile, slot, chunk0, nch;
    if (bid < 200) {
        tile   = bid / 5;
        slot   = bid - tile * 5;
        nch    = (slot < 4) ? 13 : 12;
        chunk0 = slot * 13;
    } else {
        const int b2 = bid - 200;
        tile   = 40 + (b2 >> 2);
        slot   = b2 & 3;
        nch    = 16;
        chunk0 = slot << 4;
    }
    const int p0 = tile * TILE_P;
    const int k0 = chunk0 * KC;

    // per-thread A load mapping: i = tid + j*256 -> row i>>5, si = i&31
    const int a_r  = tid >> 5;            // + j*8
    const int a_si = tid & 31;

    float accL[4][4], accH[4][4];
    #pragma unroll
    for (int j = 0; j < 4; ++j)
        #pragma unroll
        for (int q = 0; q < 4; ++q) { accL[j][q] = 0.f; accH[j][q] = 0.f; }

    int4 av[8];                            // raw A for the NEXT chunk (reg d-buffer)
    auto ldgA = [&](int c) {
        const int kc = k0 + c * KC;
        #pragma unroll
        for (int j = 0; j < 8; ++j)
            av[j] = *(const int4*)(packed + (long)(p0 + a_r + j * 8) * IC + kc + a_si * 4);
    };
    // pack + store av (chunk c) into byte-packed stage c&1
    auto stsA = [&](int c) {
        const uint32_t pa = smem_b32 + (c & 1) * PA_STAGE;
        #pragma unroll
        for (int j = 0; j < 8; ++j) {
            const uint32_t p = __byte_perm(__byte_perm(av[j].x, av[j].y, 0x0040),
                                           __byte_perm(av[j].z, av[j].w, 0x0040), 0x5410);
            asm volatile("st.shared.b32 [%0], %1;"
                         :: "r"(pa + (uint32_t)((a_r + j * 8) * PA_STRIDE + a_si * 4)),
                            "r"(p) : "memory");
        }
    };
    auto issueB = [&](int c) {
        const uint32_t sb = smem_b32 + SMEM_B_OFF + (c & 1) * STAGE_B_BYTES;
        const int kc = k0 + c * KC;
        #pragma unroll
        for (int j = 0; j < 4; ++j) {               // B: 64 rows x 256B
            const int i = tid + j * 256;
            const int r = i >> 4, si = i & 15;
            cp16(sb + (uint32_t)(r * SB_STRIDE + si * 8) * 2,
                 g_xh + (long)r * IC + kc + si * 8);
        }
        CP_COMMIT();
    };

    ldgA(0);
    issueB(0);
    for (int c = 0; c < nch; ++c) {
        stsA(c);                          // stage c&1 free since sync at c-1 bottom
        if (c + 1 < nch) issueB(c + 1);
        else CP_COMMIT();                 // keep group count uniform
        CP_WAIT1();                       // B chunk c resident
        __syncthreads();                  // all STS-A visible; B stage safe
        if (c + 1 < nch) ldgA(c + 1);     // consumed next iter: full-chunk latency cover

        const char* PA = smem + (c & 1) * PA_STAGE;
        const char* B  = smem + SMEM_B_OFF + (c & 1) * STAGE_B_BYTES;

        #pragma unroll
        for (int kk = 0; kk < 8; ++kk) {
            uint32_t afl[4], afh[4];
            #pragma unroll
            for (int kh = 0; kh < 2; ++kh) {
                #pragma unroll
                for (int hr = 0; hr < 2; ++hr) {
                    // two packed bytes: k = kk*16 + 2t + kh*8 (+1)
                    const uint32_t v = *(const uint16_t*)(PA
                        + (wr * 16 + g + hr * 8) * PA_STRIDE + kk * 16 + 2 * t + kh * 8);
                    const int idx = hr + 2 * kh;
                    afl[idx] = ((v << 4) & 0xF0u) | ((v << 12) & 0xF00000u) | 0x54005400u;
                    afh[idx] = (v & 0xF0u)        | ((v << 8)  & 0xF00000u) | 0x54005400u;
                }
            }
            #pragma unroll
            for (int nf = 0; nf < 4; ++nf) {
                const int n = wc * 32 + nf * 8 + g;
                uint32_t bf[2];
                bf[0] = *(const uint32_t*)(B + (n * SB_STRIDE + kk * 16 + 2 * t) * 2);
                bf[1] = *(const uint32_t*)(B + (n * SB_STRIDE + kk * 16 + 2 * t + 8) * 2);
                mma16816(accL[nf], afl, bf);
                mma16816(accH[nf], afh, bf);
            }
        }
        __syncthreads();
    }

    // ---- epilogue: transpose through smem, then coalesced float4 stores ----
    float* sm = (float*)smem;                  // [64 b][132] (pad 4) = 33792B <= 52224
    #pragma unroll
    for (int nf = 0; nf < 4; ++nf)
        #pragma unroll
        for (int q = 0; q < 4; ++q) {
            const int mrow = wr * 16 + g + (q >> 1) * 8;              // 0..63
            const int b    = wc * 32 + nf * 8 + 2 * t + (q & 1);      // 0..63
            sm[b * 132 + mrow]      = accL[nf][q];                    // low nibble
            sm[b * 132 + 64 + mrow] = accH[nf][q];                    // high nibble
        }
    __syncthreads();
    #pragma unroll
    for (int j = 0; j < 8; ++j) {
        const int i = tid + j * 256;           // 2048 float4
        const int b  = i >> 5;
        const int mv = (i & 31) * 4;
        const float4 v = *(const float4*)(sm + b * 132 + mv);
        const long oc = (mv < 64) ? (long)(p0 + mv) : (long)(PROWS + p0 + mv - 64);
        *(float4*)(g_partial + (((long)(slot * BATCH + b)) << 13) + oc) = v;
    }
}

// ---------------------------------------------------------------------------
// Kernel 3: sum the 5 k-slots + affine epilogue (vectorized float4 over oc)
//   out[b,oc] = delta[oc] * (dot' - (zp[oc]+64)*S_h[b]) + bias[oc]
// ---------------------------------------------------------------------------
__global__ void reduce_kernel(const float* __restrict__ delta,
                              const float* __restrict__ zp,
                              const float* __restrict__ bias,
                              float* __restrict__ out) {
    const int idx4 = (blockIdx.x * 256 + threadIdx.x) * 4;  // b*8192 + oc
    const int b  = idx4 >> 13;
    const int oc = idx4 & (OC - 1);
    float4 dot = make_float4(0.f, 0.f, 0.f, 0.f);
    #pragma unroll
    for (int s = 0; s < NSLOT; ++s) {
        const float4 p = *(const float4*)(g_partial + (long)(s * BATCH + b) * OC + oc);
        dot.x += p.x; dot.y += p.y; dot.z += p.z; dot.w += p.w;
    }
    float S = 0.f;
    #pragma unroll
    for (int j = 0; j < 8; ++j) S += g_Spart[b * 8 + j];
    const float4 d  = *(const float4*)(delta + oc);
    const float4 z  = *(const float4*)(zp + oc);
    const float4 bi = *(const float4*)(bias + oc);
    float4 o;
    o.x = d.x * (dot.x - (z.x + 64.f) * S) + bi.x;
    o.y = d.y * (dot.y - (z.y + 64.f) * S) + bi.y;
    o.z = d.z * (dot.z - (z.z + 64.f) * S) + bi.z;
    o.w = d.w * (dot.w - (z.w + 64.f) * S) + bi.w;
    *(float4*)(out + idx4) = o;
}

// ---------------------------------------------------------------------------
// Launch
// ---------------------------------------------------------------------------
extern "C" void kernel_launch(void* const* d_in, const int* in_sizes, int n_in,
                              void* d_out, int out_size) {
    const float* x      = (const float*)d_in[0];
    const int*   packed = (const int*)d_in[1];
    const float* delta  = (const float*)d_in[2];
    const float* zp     = (const float*)d_in[3];
    const float* bias   = (const float*)d_in[4];
    float* out = (float*)d_out;

    cudaFuncSetAttribute(gemm_kernel, cudaFuncAttributeMaxDynamicSharedMemorySize, SMEM_TOTAL);

    prep_kernel<<<512, 256>>>(x);
    gemm_kernel<<<296, 256, SMEM_TOTAL>>>(packed);
    reduce_kernel<<<(BATCH * OC) / 1024, 256>>>(delta, zp, bias, out);
}